// round 3
// baseline (speedup 1.0000x reference)
#include <cuda_runtime.h>
#include <math.h>

// Problem constants (shape-specialized)
#define Bx  64
#define Sx  128
#define Ex  1024
#define Hx  1024
#define Ox  135
#define WLx 64
#define PLx 32
#define WDx 200            // word feature dim
#define H3  (3*Hx)

// ---------------- scratch (static device globals; no allocation APIs) ------
__device__ float g_h[Bx*Hx];
__device__ float g_WtEd [Ex*Hx];        // [e][j]
__device__ float g_WtAtt[Ex*Hx];        // [e][j]
__device__ float g_WtWatt[WDx*Hx];      // [k][j]
__device__ float g_WtIh [Ox*H3];        // [k][n]
__device__ float g_WtHh [Hx*H3];        // [k][n]
__device__ float g_WtOut[H3*Ox];        // [k][o]
__device__ float g_encp [(size_t)Sx*Bx*Hx];   // [s][b][j]
__device__ float g_wordp[(size_t)WLx*Bx*Hx];  // [w][b][j]
__device__ float g_Ci[Bx*H3];
__device__ float g_Ch[Bx*H3];
__device__ float g_ctx [Bx*Hx];
__device__ float g_wctx[Bx*Hx];

// ---------------- transpose: dst[c*R + r] = src[r*C + c] -------------------
__global__ void transpose_kernel(float* dst, const float* src, int R, int C) {
    __shared__ float t[32][33];
    int c0 = blockIdx.x * 32, r0 = blockIdx.y * 32;
    int x = threadIdx.x, y = threadIdx.y;           // blockDim (32,8)
    #pragma unroll
    for (int i = 0; i < 32; i += 8) {
        int r = r0 + y + i, c = c0 + x;
        t[y + i][x] = (r < R && c < C) ? src[(size_t)r * C + c] : 0.f;
    }
    __syncthreads();
    #pragma unroll
    for (int i = 0; i < 32; i += 8) {
        int r = r0 + x, c = c0 + y + i;
        if (r < R && c < C) dst[(size_t)c * R + r] = t[x][y + i];
    }
}

// ---------------- generic tiled GEMM core ---------------------------------
// C[M,N] (+)= A[M,Kt] @ Bt[Kt,N], A given as up to 3 row-major K-segments.
struct ASegs { const float* A0; int K0; const float* A1; int K1; const float* A2; int K2; };

__device__ __forceinline__ float aload(const ASegs& A, int m, int k) {
    if (k < A.K0) return A.A0[(size_t)m * A.K0 + k];
    k -= A.K0;
    if (k < A.K1) return A.A1[(size_t)m * A.K1 + k];
    k -= A.K1;
    return A.A2[(size_t)m * A.K2 + k];
}

__device__ void gemm_tile(const ASegs A, int M, const float* Bt, int ldb, int N,
                          const float* bias, float* C, int ldc,
                          int mTile, int nTile, int kBeg, int kEnd, bool atomic)
{
    __shared__ __align__(16) float As[16][68];   // [k][m], padded, 16B-aligned rows
    __shared__ __align__(16) float Bs[16][64];   // [k][n]
    float acc[4][4];
    #pragma unroll
    for (int i = 0; i < 4; i++)
        #pragma unroll
        for (int j = 0; j < 4; j++) acc[i][j] = 0.f;

    int tid = threadIdx.x;              // 256 threads
    int tx = tid & 15, ty = tid >> 4;

    for (int k0 = kBeg; k0 < kEnd; k0 += 16) {
        #pragma unroll
        for (int u = 0; u < 4; u++) {   // A tile 64m x 16k
            int e = tid + u * 256;
            int m = e >> 4, kk = e & 15;
            int gk = k0 + kk, gm = mTile + m;
            float v = 0.f;
            if (gk < kEnd && gm < M) v = aload(A, gm, gk);
            As[kk][m] = v;
        }
        #pragma unroll
        for (int u = 0; u < 4; u++) {   // B tile 16k x 64n
            int e = tid + u * 256;
            int kk = e >> 6, n = e & 63;
            int gk = k0 + kk, gn = nTile + n;
            float v = 0.f;
            if (gk < kEnd && gn < N) v = Bt[(size_t)gk * ldb + gn];
            Bs[kk][n] = v;
        }
        __syncthreads();
        #pragma unroll
        for (int kk = 0; kk < 16; kk++) {
            float4 a4 = *(const float4*)&As[kk][ty * 4];
            float4 b4 = *(const float4*)&Bs[kk][tx * 4];
            float a[4] = {a4.x, a4.y, a4.z, a4.w};
            float bv[4] = {b4.x, b4.y, b4.z, b4.w};
            #pragma unroll
            for (int i = 0; i < 4; i++)
                #pragma unroll
                for (int j = 0; j < 4; j++)
                    acc[i][j] += a[i] * bv[j];
        }
        __syncthreads();
    }
    #pragma unroll
    for (int i = 0; i < 4; i++) {
        int gm = mTile + ty * 4 + i;
        if (gm >= M) continue;
        #pragma unroll
        for (int j = 0; j < 4; j++) {
            int gn = nTile + tx * 4 + j;
            if (gn >= N) continue;
            if (atomic) atomicAdd(&C[(size_t)gm * ldc + gn], acc[i][j]);
            else        C[(size_t)gm * ldc + gn] = acc[i][j] + (bias ? bias[gn] : 0.f);
        }
    }
}

__global__ void __launch_bounds__(256) gemm_kernel(
    const float* A0, int K0, const float* A1, int K1, const float* A2, int K2,
    const float* Bt, int ldb, int N, const float* bias, float* C, int ldc, int M)
{
    ASegs A{A0, K0, A1, K1, A2, K2};
    int Kt = K0 + K1 + K2;
    int G = gridDim.z;
    int chunk = (Kt + G - 1) / G;
    int kBeg = blockIdx.z * chunk;
    int kEnd = min(Kt, kBeg + chunk);
    gemm_tile(A, M, Bt, ldb, N, bias, C, ldc,
              blockIdx.y * 64, blockIdx.x * 64, kBeg, kEnd, G > 1);
}

// ---------------- fused GRU input+hidden GEMM ------------------------------
// z==0:      g_Ci = x @ W_ihT + b_ih      (store)
// z in 1..G: g_Ch += h @ W_hhT chunk      (atomic; g_Ch pre-seeded with b_hh)
__global__ void __launch_bounds__(256) gru_gemm_kernel(const float* x, const float* b_ih)
{
    int z = blockIdx.z;
    if (z == 0) {
        ASegs A{x, Ox, nullptr, 0, nullptr, 0};
        gemm_tile(A, Bx, g_WtIh, H3, H3, b_ih, g_Ci, H3,
                  0, blockIdx.x * 64, 0, Ox, false);
    } else {
        int GS = gridDim.z - 1;
        int chunk = (Hx + GS - 1) / GS;
        int kBeg = (z - 1) * chunk, kEnd = min(Hx, kBeg + chunk);
        ASegs A{g_h, Hx, nullptr, 0, nullptr, 0};
        gemm_tile(A, Bx, g_WtHh, H3, H3, nullptr, g_Ch, H3,
                  0, blockIdx.x * 64, kBeg, kEnd, true);
    }
}

// ---------------- GRU gates (in-place h update) ----------------------------
// Also re-seeds g_Ch with b_hh for the next step's atomic split-K GEMM, and
// seeds the output pose slice with b_out for the output GEMM's atomics.
__global__ void gates_kernel(const float* b_hh, float* pose_slice, const float* b_out)
{
    int b = blockIdx.x, tid = threadIdx.x;
    #pragma unroll
    for (int u = 0; u < 4; u++) {
        int j = u * 256 + tid;
        float ir = g_Ci[b*H3 + j];
        float iz = g_Ci[b*H3 + Hx + j];
        float in = g_Ci[b*H3 + 2*Hx + j];
        float hr = g_Ch[b*H3 + j];
        float hz = g_Ch[b*H3 + Hx + j];
        float hn = g_Ch[b*H3 + 2*Hx + j];
        float r  = 1.f / (1.f + __expf(-(ir + hr)));
        float zz = 1.f / (1.f + __expf(-(iz + hz)));
        float nn = tanhf(in + r * hn);
        float hv = g_h[b*Hx + j];
        g_h[b*Hx + j] = (1.f - zz) * nn + zz * hv;
        g_Ch[b*H3 + j]        = b_hh[j];
        g_Ch[b*H3 + Hx + j]   = b_hh[Hx + j];
        g_Ch[b*H3 + 2*Hx + j] = b_hh[2*Hx + j];
    }
    if (pose_slice && tid < Ox) pose_slice[b*Ox + tid] = b_out[tid];
}

__global__ void initCh_kernel(const float* b_hh) {
    int i = blockIdx.x * 256 + threadIdx.x;
    if (i < Bx * H3) g_Ch[i] = b_hh[i % H3];
}

// ---------------- one-pass online-softmax attention ------------------------
// blocks 0..63: encoder attention (S=128) -> g_ctx
// blocks 64..127: word attention (S=64)   -> g_wctx
// Each projection element is read ONCE (kept in registers for both the score
// dot-product and the weighted accumulation).
__global__ void __launch_bounds__(256) attn_kernel()
{
    int bb = blockIdx.x;
    bool isWord = bb >= Bx;
    int b = bb & (Bx - 1);
    const float* P = isWord ? g_wordp : g_encp;
    int Slen = isWord ? WLx : Sx;
    float* out = isWord ? g_wctx : g_ctx;

    __shared__ float h_s[Hx];
    __shared__ float red[8][9];
    __shared__ float sc[8];

    int tid = threadIdx.x;
    int lane = tid & 31, warp = tid >> 5;
    for (int i = tid; i < Hx; i += 256) h_s[i] = g_h[b*Hx + i];
    __syncthreads();

    float m = -1e30f, l = 0.f;
    float acc[4] = {0.f, 0.f, 0.f, 0.f};

    for (int s0 = 0; s0 < Slen; s0 += 8) {
        float ep[8][4];
        float pd[8];
        #pragma unroll
        for (int cc = 0; cc < 8; cc++) {
            const float* row = P + ((size_t)(s0 + cc) * Bx + b) * Hx;
            float d = 0.f;
            #pragma unroll
            for (int i = 0; i < 4; i++) {
                float v = row[tid + 256 * i];
                ep[cc][i] = v;
                d += v * h_s[tid + 256 * i];
            }
            pd[cc] = d;
        }
        #pragma unroll
        for (int cc = 0; cc < 8; cc++) {
            float v = pd[cc];
            v += __shfl_xor_sync(0xffffffffu, v, 16);
            v += __shfl_xor_sync(0xffffffffu, v, 8);
            v += __shfl_xor_sync(0xffffffffu, v, 4);
            v += __shfl_xor_sync(0xffffffffu, v, 2);
            v += __shfl_xor_sync(0xffffffffu, v, 1);
            if (lane == 0) red[warp][cc] = v;
        }
        __syncthreads();
        if (tid < 8) {
            float v = 0.f;
            #pragma unroll
            for (int w = 0; w < 8; w++) v += red[w][tid];
            sc[tid] = v;
        }
        __syncthreads();
        float mx = m;
        #pragma unroll
        for (int cc = 0; cc < 8; cc++) mx = fmaxf(mx, sc[cc]);
        float alpha = __expf(m - mx);
        float p[8]; float ls = 0.f;
        #pragma unroll
        for (int cc = 0; cc < 8; cc++) { p[cc] = __expf(sc[cc] - mx); ls += p[cc]; }
        l = l * alpha + ls;
        #pragma unroll
        for (int i = 0; i < 4; i++) {
            float a = acc[i] * alpha;
            #pragma unroll
            for (int cc = 0; cc < 8; cc++) a += p[cc] * ep[cc][i];
            acc[i] = a;
        }
        m = mx;
        __syncthreads();
    }
    float inv = 1.f / l;
    #pragma unroll
    for (int i = 0; i < 4; i++) out[b*Hx + tid + 256 * i] = acc[i] * inv;
}

// ---------------- host launcher --------------------------------------------
extern "C" void kernel_launch(void* const* d_in, const int* in_sizes, int n_in,
                              void* d_out, int out_size)
{
    const float* enc_states = (const float*)d_in[0];
    const float* enc_hidden = (const float*)d_in[1];
    const float* prev_poses = (const float*)d_in[2];
    const float* words      = (const float*)d_in[3];
    // d_in[4] = real_poses_len (derived from out_size instead; can't read device mem in capture)
    const float* W_ed  = (const float*)d_in[5];
    const float* b_ed  = (const float*)d_in[6];
    const float* W_att = (const float*)d_in[7];
    const float* b_att = (const float*)d_in[8];
    const float* W_watt= (const float*)d_in[9];
    const float* b_watt= (const float*)d_in[10];
    const float* W_ih  = (const float*)d_in[11];
    const float* W_hh  = (const float*)d_in[12];
    const float* b_ih  = (const float*)d_in[13];
    const float* b_hh  = (const float*)d_in[14];
    const float* W_out = (const float*)d_in[15];
    const float* b_out = (const float*)d_in[16];
    float* out = (float*)d_out;
    int T = out_size / (Bx * Ox);
    if (T < 1) T = 1;

    float *pWtEd, *pWtAtt, *pWtWatt, *pWtIh, *pWtHh, *pWtOut;
    float *pH, *pEncp, *pWordp, *pCtx, *pWctx;
    cudaGetSymbolAddress((void**)&pWtEd,  g_WtEd);
    cudaGetSymbolAddress((void**)&pWtAtt, g_WtAtt);
    cudaGetSymbolAddress((void**)&pWtWatt,g_WtWatt);
    cudaGetSymbolAddress((void**)&pWtIh,  g_WtIh);
    cudaGetSymbolAddress((void**)&pWtHh,  g_WtHh);
    cudaGetSymbolAddress((void**)&pWtOut, g_WtOut);
    cudaGetSymbolAddress((void**)&pH,     g_h);
    cudaGetSymbolAddress((void**)&pEncp,  g_encp);
    cudaGetSymbolAddress((void**)&pWordp, g_wordp);
    cudaGetSymbolAddress((void**)&pCtx,   g_ctx);
    cudaGetSymbolAddress((void**)&pWctx,  g_wctx);

    dim3 tb(32, 8);
    // Weight transposes (dst[c*R + r] = src[r*C + c])
    transpose_kernel<<<dim3(32, 32), tb>>>(pWtEd,  W_ed,  Hx,  Ex);   // (1024,1024)
    transpose_kernel<<<dim3(32, 32), tb>>>(pWtAtt, W_att, Hx,  Ex);
    transpose_kernel<<<dim3(7,  32), tb>>>(pWtWatt,W_watt,Hx,  WDx);  // (1024,200)
    transpose_kernel<<<dim3(5,  96), tb>>>(pWtIh,  W_ih,  H3,  Ox);   // (3072,135)
    transpose_kernel<<<dim3(32, 96), tb>>>(pWtHh,  W_hh,  H3,  Hx);   // (3072,1024)
    transpose_kernel<<<dim3(96, 5),  tb>>>(pWtOut, W_out, Ox,  H3);   // (135,3072)

    initCh_kernel<<<(Bx*H3 + 255)/256, 256>>>(b_hh);

    // h0 = [eh0 | eh1] @ W_edT + b_ed     (A split into two K=512 segments)
    gemm_kernel<<<dim3(16, 1, 1), 256>>>(enc_hidden, Ex/2,
                                         enc_hidden + (size_t)Bx*(Ex/2), Ex/2,
                                         nullptr, 0,
                                         pWtEd, Hx, Hx, b_ed, pH, Hx, Bx);
    // enc_proj = encoder_states @ W_attT + b_att   (M = S*B = 8192)
    gemm_kernel<<<dim3(16, 128, 1), 256>>>(enc_states, Ex, nullptr, 0, nullptr, 0,
                                           pWtAtt, Hx, Hx, b_att, pEncp, Hx, Sx*Bx);
    // word_proj = words @ W_wattT + b_watt         (M = WL*B = 4096)
    gemm_kernel<<<dim3(16, 64, 1), 256>>>(words, WDx, nullptr, 0, nullptr, 0,
                                          pWtWatt, Hx, Hx, b_watt, pWordp, Hx, WLx*Bx);

    // Warm-up scan over previous_poses
    for (int t = 0; t < PLx; t++) {
        gru_gemm_kernel<<<dim3(48, 1, 7), 256>>>(prev_poses + (size_t)t*Bx*Ox, b_ih);
        gates_kernel<<<Bx, 256>>>(b_hh, nullptr, b_out);
    }

    // Decode loop
    for (int t = 0; t < T; t++) {
        const float* x = (t == 0) ? prev_poses + (size_t)(PLx - 1)*Bx*Ox
                                  : out + (size_t)(t - 1)*Bx*Ox;
        float* pose_t = out + (size_t)t*Bx*Ox;
        gru_gemm_kernel<<<dim3(48, 1, 7), 256>>>(x, b_ih);
        gates_kernel<<<Bx, 256>>>(b_hh, pose_t, b_out);      // h update + seed pose_t=b_out
        attn_kernel<<<128, 256>>>();                          // enc + word attention together
        // pose_t += [h | ctx | wctx] @ W_outT   (split-K=12, atomic into seeded pose_t)
        gemm_kernel<<<dim3(3, 1, 12), 256>>>(pH, Hx, pCtx, Hx, pWctx, Hx,
                                             pWtOut, Ox, Ox, nullptr, pose_t, Ox, Bx);
    }
}